// round 7
// baseline (speedup 1.0000x reference)
#include <cuda_runtime.h>
#include <stdint.h>

#define S   128
#define B   256
#define H   16
#define NB  12
#define LUT_WORDS 128
#define THRESH 8

#define N_TOKENS  (S * B)              // 32768
#define N_MEMORY  (H * B * (1 << NB))  // 16777216
#define N_CONN    (H * B * NB)         // 49152

__device__ uint8_t  g_headres[H * B * S];   // [h][n][i]
__device__ unsigned g_count[B];             // last-block counters (self-resetting)
__device__ uint32_t g_tokpack[S * 8];       // bit-packed tokens [row][word]

// Connection entry may be int32 or float32 bits; range [0,519). Float bits of
// any value >= 1.0 exceed 518, so the test is unambiguous.
__device__ __forceinline__ int decode_conn(uint32_t raw) {
    return (raw <= 518u) ? (int)raw : (int)__uint_as_float(raw);
}

// Pack tokens[S][B] (0/1 words) into bitmaps: 128 warps, one row each.
__global__ __launch_bounds__(128) void pack_tokens(const uint32_t* __restrict__ tokens)
{
    const int gw   = blockIdx.x * 4 + (threadIdx.x >> 5);  // global warp = row
    const int lane = threadIdx.x & 31;
    #pragma unroll
    for (int w = 0; w < 8; w++) {
        uint32_t v   = tokens[gw * B + w * 32 + lane];
        uint32_t bal = __ballot_sync(0xffffffffu, v != 0u);
        if (lane == 0) g_tokpack[gw * 8 + w] = bal;
    }
}

// One block per (h, n). 128 threads; thread t owns query row i = t.
// Last block to finish for a given n also performs the head-majority reduce.
__global__ __launch_bounds__(128) void soft_ram_main(
    const float*    __restrict__ memory,       // [H,B,4096] f32
    const uint32_t* __restrict__ connections,  // [H,B,NB]
    float*          __restrict__ out)          // [S,B] f32
{
    __shared__ __align__(16) uint32_t s_lut[LUT_WORDS];
    __shared__ __align__(16) uint32_t s_Ak[S];
    __shared__ uint32_t s_Ap[S];
    __shared__ uint32_t s_tok[S * 9];          // padded rows (conflict-free)
    __shared__ int s_last;

    const int blk = blockIdx.x;
    const int h = blk >> 8;
    const int n = blk & 255;
    const int t = threadIdx.x;
    const int warp = t >> 5, lane = t & 31;

    // Stage this thread's packed token row (coalesced 32B per thread).
    {
        const uint4* src = (const uint4*)g_tokpack;
        uint4 a = src[t * 2], b = src[t * 2 + 1];
        s_tok[t * 9 + 0] = a.x; s_tok[t * 9 + 1] = a.y;
        s_tok[t * 9 + 2] = a.z; s_tok[t * 9 + 3] = a.w;
        s_tok[t * 9 + 4] = b.x; s_tok[t * 9 + 5] = b.y;
        s_tok[t * 9 + 6] = b.z; s_tok[t * 9 + 7] = b.w;
    }

    // Binarize this neuron's 4096-float LUT into a 512B bitmap.
    const float* mem = memory + ((size_t)(h * B + n) << NB);
    for (int w = warp; w < LUT_WORDS; w += 4) {
        uint32_t bal = __ballot_sync(0xffffffffu, mem[(w << 5) + lane] > 0.0f);
        if (lane == 0) s_lut[w] = bal;
    }
    __syncthreads();

    // Decomposed address parts: addr(i,j) = Aq[i] | Ak[j] | Ap[i-j].
    // has_pos is block-uniform (depends only on conn).
    const uint32_t* conn = connections + (size_t)(h * B + n) * NB;
    uint32_t aq = 0, ak = 0, ap = 0;
    bool has_pos = false;
    #pragma unroll
    for (int b = 0; b < NB; b++) {
        int c = decode_conn(conn[b]);
        if (c < B) {
            aq |= ((s_tok[t * 9 + (c >> 5)] >> (c & 31)) & 1u) << b;
        } else if (c < 2 * B) {
            int cc = c - B;
            ak |= ((s_tok[t * 9 + (cc >> 5)] >> (cc & 31)) & 1u) << b;
        } else {
            ap |= ((uint32_t)(t >> (c - 2 * B)) & 1u) << b;
            has_pos = true;
        }
    }
    s_Ak[t] = ak;
    s_Ap[t] = ap;
    __syncthreads();

    // Causal XOR accumulation over keys j <= i. Funnelshift rotates the bit of
    // interest into bit 0 (shift is mod 32); upper bits are garbage.
    uint32_t p = 0;
    const int i = t;
    int j = 0;
    const int full = (i + 1) & ~3;

    if (!has_pos) {
        // ~85% of blocks: addr has no position dependence -> 2 LDS streams only.
        #pragma unroll 2
        for (; j < full; j += 4) {
            uint4 k4 = *reinterpret_cast<const uint4*>(&s_Ak[j]);  // broadcast
            uint32_t a0 = aq | k4.x;
            uint32_t a1 = aq | k4.y;
            uint32_t a2 = aq | k4.z;
            uint32_t a3 = aq | k4.w;
            uint32_t w0 = s_lut[a0 >> 5], w1 = s_lut[a1 >> 5];
            uint32_t w2 = s_lut[a2 >> 5], w3 = s_lut[a3 >> 5];
            p ^= __funnelshift_r(w0, w0, a0) ^ __funnelshift_r(w1, w1, a1)
               ^ __funnelshift_r(w2, w2, a2) ^ __funnelshift_r(w3, w3, a3);
        }
        for (; j <= i; ++j) {
            uint32_t a = aq | s_Ak[j];
            uint32_t w = s_lut[a >> 5];
            p ^= __funnelshift_r(w, w, a);
        }
    } else {
        #pragma unroll 2
        for (; j < full; j += 4) {
            uint4 k4 = *reinterpret_cast<const uint4*>(&s_Ak[j]);
            uint32_t a0 = aq | k4.x | s_Ap[i - j];
            uint32_t a1 = aq | k4.y | s_Ap[i - j - 1];
            uint32_t a2 = aq | k4.z | s_Ap[i - j - 2];
            uint32_t a3 = aq | k4.w | s_Ap[i - j - 3];
            uint32_t w0 = s_lut[a0 >> 5], w1 = s_lut[a1 >> 5];
            uint32_t w2 = s_lut[a2 >> 5], w3 = s_lut[a3 >> 5];
            p ^= __funnelshift_r(w0, w0, a0) ^ __funnelshift_r(w1, w1, a1)
               ^ __funnelshift_r(w2, w2, a2) ^ __funnelshift_r(w3, w3, a3);
        }
        for (; j <= i; ++j) {
            uint32_t a = aq | s_Ak[j] | s_Ap[i - j];
            uint32_t w = s_lut[a >> 5];
            p ^= __funnelshift_r(w, w, a);
        }
    }

    g_headres[(size_t)(h * B + n) * S + t] = (uint8_t)(p & 1u);

    // Last-block-per-n reduce (threadFenceReduction pattern).
    __threadfence();
    if (t == 0) {
        unsigned old = atomicAdd(&g_count[n], 1u);
        s_last = (old == H - 1) ? 1 : 0;
    }
    __syncthreads();
    if (s_last) {
        __threadfence();
        int ssum = 0;
        #pragma unroll
        for (int hh = 0; hh < H; hh++)
            ssum += g_headres[(size_t)(hh * B + n) * S + t];
        out[t * B + n] = (ssum > THRESH) ? 1.0f : 0.0f;
        if (t == 0) g_count[n] = 0;   // reset for next graph replay
    }
}

extern "C" void kernel_launch(void* const* d_in, const int* in_sizes, int n_in,
                              void* d_out, int out_size)
{
    const uint32_t* tokens      = 0;
    const float*    memory      = 0;
    const uint32_t* connections = 0;

    for (int k = 0; k < n_in; k++) {
        if      (in_sizes[k] == N_TOKENS && !tokens)      tokens      = (const uint32_t*)d_in[k];
        else if (in_sizes[k] == N_MEMORY && !memory)      memory      = (const float*)d_in[k];
        else if (in_sizes[k] == N_CONN   && !connections) connections = (const uint32_t*)d_in[k];
    }
    for (int k = 0; k < n_in; k++) {
        if      (in_sizes[k] == N_TOKENS * 4 && !tokens)      tokens      = (const uint32_t*)d_in[k];
        else if (in_sizes[k] == N_MEMORY * 4 && !memory)      memory      = (const float*)d_in[k];
        else if (in_sizes[k] == N_CONN * 4   && !connections) connections = (const uint32_t*)d_in[k];
    }
    if (!tokens || !memory || !connections) {
        tokens      = (const uint32_t*)d_in[0];
        memory      = (const float*)d_in[1];
        connections = (const uint32_t*)d_in[2];
    }

    pack_tokens<<<32, 128>>>(tokens);
    soft_ram_main<<<H * B, 128>>>(memory, connections, (float*)d_out);
}

// round 8
// speedup vs baseline: 1.0390x; 1.0390x over previous
#include <cuda_runtime.h>
#include <stdint.h>

#define S   128
#define B   256
#define H   16
#define NB  12
#define LUT_WORDS 128
#define THRESH 8

#define N_TOKENS  (S * B)              // 32768
#define N_MEMORY  (H * B * (1 << NB))  // 16777216
#define N_CONN    (H * B * NB)         // 49152

__device__ uint8_t  g_headres[H * B * S];
__device__ unsigned g_count[B];
__device__ uint32_t g_tokpack[S * 8];

__device__ __forceinline__ int decode_conn(uint32_t raw) {
    return (raw <= 518u) ? (int)raw : (int)__uint_as_float(raw);
}

__global__ __launch_bounds__(128) void pack_tokens(const uint32_t* __restrict__ tokens)
{
    const int gw   = blockIdx.x * 4 + (threadIdx.x >> 5);
    const int lane = threadIdx.x & 31;
    #pragma unroll
    for (int w = 0; w < 8; w++) {
        uint32_t v   = tokens[gw * B + w * 32 + lane];
        uint32_t bal = __ballot_sync(0xffffffffu, v != 0u);
        if (lane == 0) g_tokpack[gw * 8 + w] = bal;
    }
}

// One block per (h, n). 128 threads; thread t owns query row i = t.
__global__ __launch_bounds__(128) void soft_ram_main(
    const float*    __restrict__ memory,
    const uint32_t* __restrict__ connections,
    float*          __restrict__ out)
{
    __shared__ __align__(16) uint32_t s_lut[LUT_WORDS];
    __shared__ __align__(16) uint32_t s_Ak[S];
    __shared__ uint32_t s_Ap[S];
    __shared__ uint32_t s_tok[S * 9];
    __shared__ uint32_t s_R[LUT_WORDS];       // permuted LUT (x_q:x_k order)
    __shared__ uint32_t s_exp_hi[128];        // expand compact bits 5..11
    __shared__ uint32_t s_exp_lo[32];         // expand compact bits 0..4
    __shared__ int s_kpos[NB], s_qpos[NB];    // address bit positions by type
    __shared__ uint32_t s_wsum[4 * 4];        // per-warp scan totals
    __shared__ int s_last;

    const int blk = blockIdx.x;
    const int h = blk >> 8;
    const int n = blk & 255;
    const int t = threadIdx.x;
    const int warp = t >> 5, lane = t & 31;

    // Stage packed token row (coalesced; each thread reads/writes its own row).
    {
        const uint4* src = (const uint4*)g_tokpack;
        uint4 a = src[t * 2], b = src[t * 2 + 1];
        s_tok[t * 9 + 0] = a.x; s_tok[t * 9 + 1] = a.y;
        s_tok[t * 9 + 2] = a.z; s_tok[t * 9 + 3] = a.w;
        s_tok[t * 9 + 4] = b.x; s_tok[t * 9 + 5] = b.y;
        s_tok[t * 9 + 6] = b.z; s_tok[t * 9 + 7] = b.w;
    }

    // Binarize LUT into 4096-bit bitmap.
    const float* mem = memory + ((size_t)(h * B + n) << NB);
    for (int w = warp; w < LUT_WORDS; w += 4) {
        uint32_t bal = __ballot_sync(0xffffffffu, mem[(w << 5) + lane] > 0.0f);
        if (lane == 0) s_lut[w] = bal;
    }

    // Decode connections: addr(i,j) = Aq[i] | Ak[j] | Ap[i-j].
    // Also build compact indices xq, xk and bit-position lists (block-uniform:
    // all threads write identical values to s_kpos/s_qpos -> benign).
    const uint32_t* conn = connections + (size_t)(h * B + n) * NB;
    uint32_t aq = 0, ak = 0, ap = 0, xk = 0, xq = 0;
    int kc = 0, qc = 0;
    bool haspos = false;
    #pragma unroll
    for (int b = 0; b < NB; b++) {
        int c = decode_conn(conn[b]);
        if (c < B) {
            uint32_t bit = (s_tok[t * 9 + (c >> 5)] >> (c & 31)) & 1u;
            aq |= bit << b;
            xq |= bit << qc;
            s_qpos[qc] = b;
            qc++;
        } else if (c < 2 * B) {
            int cc = c - B;
            uint32_t bit = (s_tok[t * 9 + (cc >> 5)] >> (cc & 31)) & 1u;
            ak |= bit << b;
            xk |= bit << kc;
            s_kpos[kc] = b;
            kc++;
        } else {
            ap |= ((uint32_t)(t >> (c - 2 * B)) & 1u) << b;
            haspos = true;
        }
    }
    const int mk = kc;
    s_Ak[t] = ak;
    s_Ap[t] = ap;
    __syncthreads();   // lut, pos-lists, Ak/Ap ready

    const bool pathA = (!haspos) && (mk <= 7);   // block-uniform

    uint32_t parity;

    if (pathA) {
        // --- Expand tables: compact index -> address bits ---
        // compact bit c: c < mk -> k position; else q position (mk+mq == 12).
        {
            uint32_t e = 0;
            #pragma unroll
            for (int cb = 5; cb < 12; cb++)
                if ((t >> (cb - 5)) & 1)
                    e |= 1u << ((cb < mk) ? s_kpos[cb] : s_qpos[cb - mk]);
            s_exp_hi[t] = e;
            if (t < 32) {
                uint32_t e2 = 0;
                #pragma unroll
                for (int cb = 0; cb < 5; cb++)
                    if ((t >> cb) & 1)
                        e2 |= 1u << ((cb < mk) ? s_kpos[cb] : s_qpos[cb - mk]);
                s_exp_lo[t] = e2;
            }
        }
        __syncthreads();

        // --- Build R: permuted LUT, R bit x = L bit at expand(x) ---
        {
            const uint32_t alo = s_exp_lo[lane];
            #pragma unroll 4
            for (int wi = 0; wi < 32; wi++) {
                int w = warp * 32 + wi;
                uint32_t a = alo | s_exp_hi[w];
                uint32_t word = s_lut[a >> 5];
                uint32_t bal = __ballot_sync(0xffffffffu, (word >> (a & 31)) & 1u);
                if (lane == 0) s_R[w] = bal;
            }
        }

        // --- Inclusive prefix-XOR scan of onehot(xk) over threads (=keys) ---
        uint32_t b0 = ((xk >> 5) == 0) ? (1u << (xk & 31)) : 0u;
        uint32_t b1 = ((xk >> 5) == 1) ? (1u << (xk & 31)) : 0u;
        uint32_t b2 = ((xk >> 5) == 2) ? (1u << (xk & 31)) : 0u;
        uint32_t b3 = ((xk >> 5) == 3) ? (1u << (xk & 31)) : 0u;
        #pragma unroll
        for (int d = 1; d < 32; d <<= 1) {
            uint32_t t0 = __shfl_up_sync(0xffffffffu, b0, d);
            uint32_t t1 = __shfl_up_sync(0xffffffffu, b1, d);
            uint32_t t2 = __shfl_up_sync(0xffffffffu, b2, d);
            uint32_t t3 = __shfl_up_sync(0xffffffffu, b3, d);
            if (lane >= d) { b0 ^= t0; b1 ^= t1; b2 ^= t2; b3 ^= t3; }
        }
        if (lane == 31) {
            s_wsum[warp * 4 + 0] = b0; s_wsum[warp * 4 + 1] = b1;
            s_wsum[warp * 4 + 2] = b2; s_wsum[warp * 4 + 3] = b3;
        }
        __syncthreads();   // also orders s_R stores before product reads
        #pragma unroll
        for (int pw = 0; pw < 3; pw++)
            if (pw < warp) {
                b0 ^= s_wsum[pw * 4 + 0]; b1 ^= s_wsum[pw * 4 + 1];
                b2 ^= s_wsum[pw * 4 + 2]; b3 ^= s_wsum[pw * 4 + 3];
            }

        // --- Product: parity = popc(b & Row_xq) mod 2 ---
        uint32_t pos = xq << mk;            // < 4096
        uint32_t base = pos >> 5, sh = pos & 31;
        int cnt = __popc((s_R[base] >> sh) & b0);
        if (mk >= 6) cnt += __popc(s_R[base + 1] & b1);
        if (mk == 7) cnt += __popc(s_R[base + 2] & b2) + __popc(s_R[base + 3] & b3);
        parity = (uint32_t)cnt & 1u;
    } else {
        // --- Fallback: per-key loop (R5 form) ---
        uint32_t p = 0;
        const int i = t;
        int j = 0;
        const int full = (i + 1) & ~3;
        #pragma unroll 2
        for (; j < full; j += 4) {
            uint4 k4 = *reinterpret_cast<const uint4*>(&s_Ak[j]);
            uint32_t a0 = aq | k4.x | s_Ap[i - j];
            uint32_t a1 = aq | k4.y | s_Ap[i - j - 1];
            uint32_t a2 = aq | k4.z | s_Ap[i - j - 2];
            uint32_t a3 = aq | k4.w | s_Ap[i - j - 3];
            uint32_t w0 = s_lut[a0 >> 5], w1 = s_lut[a1 >> 5];
            uint32_t w2 = s_lut[a2 >> 5], w3 = s_lut[a3 >> 5];
            p ^= __funnelshift_r(w0, w0, a0) ^ __funnelshift_r(w1, w1, a1)
               ^ __funnelshift_r(w2, w2, a2) ^ __funnelshift_r(w3, w3, a3);
        }
        for (; j <= i; ++j) {
            uint32_t a = aq | s_Ak[j] | s_Ap[i - j];
            uint32_t w = s_lut[a >> 5];
            p ^= __funnelshift_r(w, w, a);
        }
        parity = p & 1u;
    }

    g_headres[(size_t)(h * B + n) * S + t] = (uint8_t)parity;

    // Last-block-per-n fused reduce.
    __threadfence();
    if (t == 0) {
        unsigned old = atomicAdd(&g_count[n], 1u);
        s_last = (old == H - 1) ? 1 : 0;
    }
    __syncthreads();
    if (s_last) {
        __threadfence();
        int ssum = 0;
        #pragma unroll
        for (int hh = 0; hh < H; hh++)
            ssum += g_headres[(size_t)(hh * B + n) * S + t];
        out[t * B + n] = (ssum > THRESH) ? 1.0f : 0.0f;
        if (t == 0) g_count[n] = 0;
    }
}

extern "C" void kernel_launch(void* const* d_in, const int* in_sizes, int n_in,
                              void* d_out, int out_size)
{
    const uint32_t* tokens      = 0;
    const float*    memory      = 0;
    const uint32_t* connections = 0;

    for (int k = 0; k < n_in; k++) {
        if      (in_sizes[k] == N_TOKENS && !tokens)      tokens      = (const uint32_t*)d_in[k];
        else if (in_sizes[k] == N_MEMORY && !memory)      memory      = (const float*)d_in[k];
        else if (in_sizes[k] == N_CONN   && !connections) connections = (const uint32_t*)d_in[k];
    }
    for (int k = 0; k < n_in; k++) {
        if      (in_sizes[k] == N_TOKENS * 4 && !tokens)      tokens      = (const uint32_t*)d_in[k];
        else if (in_sizes[k] == N_MEMORY * 4 && !memory)      memory      = (const float*)d_in[k];
        else if (in_sizes[k] == N_CONN * 4   && !connections) connections = (const uint32_t*)d_in[k];
    }
    if (!tokens || !memory || !connections) {
        tokens      = (const uint32_t*)d_in[0];
        memory      = (const float*)d_in[1];
        connections = (const uint32_t*)d_in[2];
    }

    pack_tokens<<<32, 128>>>(tokens);
    soft_ram_main<<<H * B, 128>>>(memory, connections, (float*)d_out);
}

// round 11
// speedup vs baseline: 1.0935x; 1.0525x over previous
#include <cuda_runtime.h>
#include <stdint.h>

#define S   128
#define B   256
#define H   16
#define NB  12
#define LUT_WORDS 128
#define THRESH 8

#define N_TOKENS  (S * B)              // 32768
#define N_MEMORY  (H * B * (1 << NB))  // 16777216
#define N_CONN    (H * B * NB)         // 49152

__device__ uint8_t  g_headres[H * B * S];
__device__ unsigned g_count[B];
__device__ uint32_t g_tokpack[S * 8];

__device__ __forceinline__ int decode_conn(uint32_t raw) {
    return (raw <= 518u) ? (int)raw : (int)__uint_as_float(raw);
}

__global__ __launch_bounds__(128) void pack_tokens(const uint32_t* __restrict__ tokens)
{
    const int gw   = blockIdx.x * 4 + (threadIdx.x >> 5);
    const int lane = threadIdx.x & 31;
    #pragma unroll
    for (int w = 0; w < 8; w++) {
        uint32_t v   = tokens[gw * B + w * 32 + lane];
        uint32_t bal = __ballot_sync(0xffffffffu, v != 0u);
        if (lane == 0) g_tokpack[gw * 8 + w] = bal;
    }
}

// One block per (h, n). 128 threads; thread t owns query row i = t.
__global__ __launch_bounds__(128) void soft_ram_main(
    const float*    __restrict__ memory,
    const uint32_t* __restrict__ connections,
    float*          __restrict__ out)
{
    __shared__ __align__(16) uint32_t s_lut[LUT_WORDS];
    __shared__ __align__(16) uint32_t s_Ak[S];
    __shared__ uint32_t s_Ap[S];
    __shared__ uint32_t s_tok[S * 9];
    __shared__ uint32_t s_R[LUT_WORDS];       // permuted LUT (x_q:x_k order)
    __shared__ uint32_t s_exp_hi[128];
    __shared__ uint32_t s_exp_lo[32];
    __shared__ int s_kpos[NB], s_qpos[NB];
    __shared__ uint32_t s_wsum[4 * 4];
    __shared__ int s_last;

    const int blk = blockIdx.x;
    const int h = blk >> 8;
    const int n = blk & 255;
    const int t = threadIdx.x;
    const int warp = t >> 5, lane = t & 31;

    // Stage packed token row (coalesced; each thread only touches row t).
    {
        const uint4* src = (const uint4*)g_tokpack;
        uint4 a = src[t * 2], b = src[t * 2 + 1];
        s_tok[t * 9 + 0] = a.x; s_tok[t * 9 + 1] = a.y;
        s_tok[t * 9 + 2] = a.z; s_tok[t * 9 + 3] = a.w;
        s_tok[t * 9 + 4] = b.x; s_tok[t * 9 + 5] = b.y;
        s_tok[t * 9 + 6] = b.z; s_tok[t * 9 + 7] = b.w;
    }

    // Binarize LUT: float4 loads + sign compare + shfl_xor OR-butterfly within
    // 8-lane segments (distances 1,2,4 never cross a segment boundary).
    {
        const float4* mem4 = (const float4*)(memory + ((size_t)(h * B + n) << NB));
        #pragma unroll
        for (int it = 0; it < 8; it++) {
            float4 v = mem4[warp * 256 + it * 32 + lane];
            uint32_t nib = (uint32_t)(v.x > 0.0f)
                         | ((uint32_t)(v.y > 0.0f) << 1)
                         | ((uint32_t)(v.z > 0.0f) << 2)
                         | ((uint32_t)(v.w > 0.0f) << 3);
            uint32_t w = nib << ((lane & 7) * 4);
            w |= __shfl_xor_sync(0xffffffffu, w, 1);
            w |= __shfl_xor_sync(0xffffffffu, w, 2);
            w |= __shfl_xor_sync(0xffffffffu, w, 4);
            if ((lane & 7) == 0) s_lut[warp * 32 + it * 4 + (lane >> 3)] = w;
        }
    }

    // Decode connections: addr(i,j) = Aq[i] | Ak[j] | Ap[i-j]; compact xq/xk.
    const uint32_t* conn = connections + (size_t)(h * B + n) * NB;
    uint32_t aq = 0, ak = 0, ap = 0, xk = 0, xq = 0;
    int kc = 0, qc = 0;
    bool haspos = false;
    #pragma unroll
    for (int b = 0; b < NB; b++) {
        int c = decode_conn(conn[b]);
        if (c < B) {
            uint32_t bit = (s_tok[t * 9 + (c >> 5)] >> (c & 31)) & 1u;
            aq |= bit << b;
            xq |= bit << qc;
            s_qpos[qc] = b;      // block-uniform value, benign race
            qc++;
        } else if (c < 2 * B) {
            int cc = c - B;
            uint32_t bit = (s_tok[t * 9 + (cc >> 5)] >> (cc & 31)) & 1u;
            ak |= bit << b;
            xk |= bit << kc;
            s_kpos[kc] = b;
            kc++;
        } else {
            ap |= ((uint32_t)(t >> (c - 2 * B)) & 1u) << b;
            haspos = true;
        }
    }
    const int mk = kc;
    s_Ak[t] = ak;
    s_Ap[t] = ap;
    __syncthreads();

    const bool pathA = (!haspos) && (mk <= 7);   // block-uniform
    uint32_t parity;

    if (pathA) {
        // Expand tables: compact index -> address bits.
        {
            uint32_t e = 0;
            #pragma unroll
            for (int cb = 5; cb < 12; cb++)
                if ((t >> (cb - 5)) & 1)
                    e |= 1u << ((cb < mk) ? s_kpos[cb] : s_qpos[cb - mk]);
            s_exp_hi[t] = e;
            if (t < 32) {
                uint32_t e2 = 0;
                #pragma unroll
                for (int cb = 0; cb < 5; cb++)
                    if ((t >> cb) & 1)
                        e2 |= 1u << ((cb < mk) ? s_kpos[cb] : s_qpos[cb - mk]);
                s_exp_lo[t] = e2;
            }
        }
        __syncthreads();

        // Build permuted LUT R: R bit x = L bit expand(x).
        {
            const uint32_t alo = s_exp_lo[lane];
            #pragma unroll 4
            for (int wi = 0; wi < 32; wi++) {
                int w = warp * 32 + wi;
                uint32_t a = alo | s_exp_hi[w];
                uint32_t word = s_lut[a >> 5];
                uint32_t bal = __ballot_sync(0xffffffffu, (word >> (a & 31)) & 1u);
                if (lane == 0) s_R[w] = bal;
            }
        }

        const uint32_t pos = xq << mk;
        const uint32_t base = pos >> 5;

        if (mk <= 5) {
            uint32_t b0 = 1u << xk;
            #pragma unroll
            for (int d = 1; d < 32; d <<= 1) {
                uint32_t t0 = __shfl_up_sync(0xffffffffu, b0, d);
                if (lane >= d) b0 ^= t0;
            }
            if (lane == 31) s_wsum[warp] = b0;
            __syncthreads();   // also orders s_R stores before product reads
            #pragma unroll
            for (int pw = 0; pw < 3; pw++)
                if (pw < warp) b0 ^= s_wsum[pw];
            parity = (uint32_t)__popc((s_R[base] >> (pos & 31)) & b0) & 1u;
        } else if (mk == 6) {
            uint32_t b0 = ((xk >> 5) == 0) ? (1u << (xk & 31)) : 0u;
            uint32_t b1 = ((xk >> 5) == 1) ? (1u << (xk & 31)) : 0u;
            #pragma unroll
            for (int d = 1; d < 32; d <<= 1) {
                uint32_t t0 = __shfl_up_sync(0xffffffffu, b0, d);
                uint32_t t1 = __shfl_up_sync(0xffffffffu, b1, d);
                if (lane >= d) { b0 ^= t0; b1 ^= t1; }
            }
            if (lane == 31) { s_wsum[warp * 2] = b0; s_wsum[warp * 2 + 1] = b1; }
            __syncthreads();
            #pragma unroll
            for (int pw = 0; pw < 3; pw++)
                if (pw < warp) { b0 ^= s_wsum[pw * 2]; b1 ^= s_wsum[pw * 2 + 1]; }
            parity = (uint32_t)(__popc(s_R[base] & b0) + __popc(s_R[base + 1] & b1)) & 1u;
        } else {  // mk == 7
            uint32_t b0 = ((xk >> 5) == 0) ? (1u << (xk & 31)) : 0u;
            uint32_t b1 = ((xk >> 5) == 1) ? (1u << (xk & 31)) : 0u;
            uint32_t b2 = ((xk >> 5) == 2) ? (1u << (xk & 31)) : 0u;
            uint32_t b3 = ((xk >> 5) == 3) ? (1u << (xk & 31)) : 0u;
            #pragma unroll
            for (int d = 1; d < 32; d <<= 1) {
                uint32_t t0 = __shfl_up_sync(0xffffffffu, b0, d);
                uint32_t t1 = __shfl_up_sync(0xffffffffu, b1, d);
                uint32_t t2 = __shfl_up_sync(0xffffffffu, b2, d);
                uint32_t t3 = __shfl_up_sync(0xffffffffu, b3, d);
                if (lane >= d) { b0 ^= t0; b1 ^= t1; b2 ^= t2; b3 ^= t3; }
            }
            if (lane == 31) {
                s_wsum[warp * 4 + 0] = b0; s_wsum[warp * 4 + 1] = b1;
                s_wsum[warp * 4 + 2] = b2; s_wsum[warp * 4 + 3] = b3;
            }
            __syncthreads();
            #pragma unroll
            for (int pw = 0; pw < 3; pw++)
                if (pw < warp) {
                    b0 ^= s_wsum[pw * 4 + 0]; b1 ^= s_wsum[pw * 4 + 1];
                    b2 ^= s_wsum[pw * 4 + 2]; b3 ^= s_wsum[pw * 4 + 3];
                }
            parity = (uint32_t)(__popc(s_R[base] & b0) + __popc(s_R[base + 1] & b1)
                              + __popc(s_R[base + 2] & b2) + __popc(s_R[base + 3] & b3)) & 1u;
        }
    } else {
        // Fallback: per-key loop.
        uint32_t p = 0;
        const int i = t;
        int j = 0;
        const int full = (i + 1) & ~3;
        #pragma unroll 2
        for (; j < full; j += 4) {
            uint4 k4 = *reinterpret_cast<const uint4*>(&s_Ak[j]);
            uint32_t a0 = aq | k4.x | s_Ap[i - j];
            uint32_t a1 = aq | k4.y | s_Ap[i - j - 1];
            uint32_t a2 = aq | k4.z | s_Ap[i - j - 2];
            uint32_t a3 = aq | k4.w | s_Ap[i - j - 3];
            uint32_t w0 = s_lut[a0 >> 5], w1 = s_lut[a1 >> 5];
            uint32_t w2 = s_lut[a2 >> 5], w3 = s_lut[a3 >> 5];
            p ^= __funnelshift_r(w0, w0, a0) ^ __funnelshift_r(w1, w1, a1)
               ^ __funnelshift_r(w2, w2, a2) ^ __funnelshift_r(w3, w3, a3);
        }
        for (; j <= i; ++j) {
            uint32_t a = aq | s_Ak[j] | s_Ap[i - j];
            uint32_t w = s_lut[a >> 5];
            p ^= __funnelshift_r(w, w, a);
        }
        parity = p & 1u;
    }

    g_headres[(size_t)(h * B + n) * S + t] = (uint8_t)parity;

    // Fused reduce — CORRECT threadfence-reduction protocol:
    // store -> fence (per-thread, device scope) -> BARRIER (all threads'
    // stores+fences done) -> single atomicAdd. Previously the barrier was
    // missing, so thread 0 could bump the counter before warps 1-3 stored.
    __threadfence();
    __syncthreads();
    if (t == 0) {
        unsigned old = atomicAdd(&g_count[n], 1u);
        s_last = (old == H - 1) ? 1 : 0;
    }
    __syncthreads();
    if (s_last) {
        __threadfence();
        int ssum = 0;
        #pragma unroll
        for (int hh = 0; hh < H; hh++)
            ssum += (int)__ldcg((const unsigned char*)&g_headres[(size_t)(hh * B + n) * S + t]);
        out[t * B + n] = (ssum > THRESH) ? 1.0f : 0.0f;
        if (t == 0) g_count[n] = 0;   // reset for next graph replay
    }
}

extern "C" void kernel_launch(void* const* d_in, const int* in_sizes, int n_in,
                              void* d_out, int out_size)
{
    const uint32_t* tokens      = 0;
    const float*    memory      = 0;
    const uint32_t* connections = 0;

    for (int k = 0; k < n_in; k++) {
        if      (in_sizes[k] == N_TOKENS && !tokens)      tokens      = (const uint32_t*)d_in[k];
        else if (in_sizes[k] == N_MEMORY && !memory)      memory      = (const float*)d_in[k];
        else if (in_sizes[k] == N_CONN   && !connections) connections = (const uint32_t*)d_in[k];
    }
    for (int k = 0; k < n_in; k++) {
        if      (in_sizes[k] == N_TOKENS * 4 && !tokens)      tokens      = (const uint32_t*)d_in[k];
        else if (in_sizes[k] == N_MEMORY * 4 && !memory)      memory      = (const float*)d_in[k];
        else if (in_sizes[k] == N_CONN * 4   && !connections) connections = (const uint32_t*)d_in[k];
    }
    if (!tokens || !memory || !connections) {
        tokens      = (const uint32_t*)d_in[0];
        memory      = (const float*)d_in[1];
        connections = (const uint32_t*)d_in[2];
    }

    pack_tokens<<<32, 128>>>(tokens);
    soft_ram_main<<<H * B, 128>>>(memory, connections, (float*)d_out);
}

// round 12
// speedup vs baseline: 1.1180x; 1.0224x over previous
#include <cuda_runtime.h>
#include <stdint.h>

#define S   128
#define B   256
#define H   16
#define NB  12
#define LUT_WORDS 128
#define THRESH 8

#define N_TOKENS  (S * B)              // 32768
#define N_MEMORY  (H * B * (1 << NB))  // 16777216
#define N_CONN    (H * B * NB)         // 49152

__device__ uint8_t  g_headres[H * B * S];
__device__ unsigned g_count[B];
__device__ uint32_t g_tokpack[S * 8];

__device__ __forceinline__ int decode_conn(uint32_t raw) {
    return (raw <= 518u) ? (int)raw : (int)__uint_as_float(raw);
}

__global__ __launch_bounds__(128) void pack_tokens(const uint32_t* __restrict__ tokens)
{
    const int gw   = blockIdx.x * 4 + (threadIdx.x >> 5);
    const int lane = threadIdx.x & 31;
    #pragma unroll
    for (int w = 0; w < 8; w++) {
        uint32_t v   = tokens[gw * B + w * 32 + lane];
        uint32_t bal = __ballot_sync(0xffffffffu, v != 0u);
        if (lane == 0) g_tokpack[gw * 8 + w] = bal;
    }
}

// One block per (h, n). 128 threads; thread t owns query row i = t.
__global__ __launch_bounds__(128) void soft_ram_main(
    const float*    __restrict__ memory,
    const uint32_t* __restrict__ connections,
    float*          __restrict__ out)
{
    __shared__ __align__(16) uint32_t s_lut[LUT_WORDS];
    __shared__ __align__(16) uint32_t s_Ak[S];
    __shared__ uint32_t s_Ap[S];
    __shared__ uint32_t s_tok[S * 9];
    __shared__ uint32_t s_R[LUT_WORDS];       // permuted LUT (x_q:x_k order)
    __shared__ uint32_t s_exp_hi[128];
    __shared__ uint32_t s_exp_lo[32];
    __shared__ int s_kpos[NB], s_qpos[NB];
    __shared__ uint32_t s_wsum[4 * 8];        // per-warp scan totals (up to 8 words)
    __shared__ int s_last;

    const int blk = blockIdx.x;
    const int h = blk >> 8;
    const int n = blk & 255;
    const int t = threadIdx.x;
    const int warp = t >> 5, lane = t & 31;

    // Stage packed token row (coalesced; each thread only touches row t).
    {
        const uint4* src = (const uint4*)g_tokpack;
        uint4 a = src[t * 2], b = src[t * 2 + 1];
        s_tok[t * 9 + 0] = a.x; s_tok[t * 9 + 1] = a.y;
        s_tok[t * 9 + 2] = a.z; s_tok[t * 9 + 3] = a.w;
        s_tok[t * 9 + 4] = b.x; s_tok[t * 9 + 5] = b.y;
        s_tok[t * 9 + 6] = b.z; s_tok[t * 9 + 7] = b.w;
    }

    // Binarize LUT: float4 loads + sign compare + shfl_xor OR-butterfly within
    // 8-lane segments (distances 1,2,4 never cross a segment boundary).
    {
        const float4* mem4 = (const float4*)(memory + ((size_t)(h * B + n) << NB));
        #pragma unroll
        for (int it = 0; it < 8; it++) {
            float4 v = mem4[warp * 256 + it * 32 + lane];
            uint32_t nib = (uint32_t)(v.x > 0.0f)
                         | ((uint32_t)(v.y > 0.0f) << 1)
                         | ((uint32_t)(v.z > 0.0f) << 2)
                         | ((uint32_t)(v.w > 0.0f) << 3);
            uint32_t w = nib << ((lane & 7) * 4);
            w |= __shfl_xor_sync(0xffffffffu, w, 1);
            w |= __shfl_xor_sync(0xffffffffu, w, 2);
            w |= __shfl_xor_sync(0xffffffffu, w, 4);
            if ((lane & 7) == 0) s_lut[warp * 32 + it * 4 + (lane >> 3)] = w;
        }
    }

    // Decode connections: addr(i,j) = Aq[i] | Ak[j] | Ap[i-j]; compact xq/xk.
    const uint32_t* conn = connections + (size_t)(h * B + n) * NB;
    uint32_t aq = 0, ak = 0, ap = 0, xk = 0, xq = 0;
    int kc = 0, qc = 0;
    bool haspos = false;
    #pragma unroll
    for (int b = 0; b < NB; b++) {
        int c = decode_conn(conn[b]);
        if (c < B) {
            uint32_t bit = (s_tok[t * 9 + (c >> 5)] >> (c & 31)) & 1u;
            aq |= bit << b;
            xq |= bit << qc;
            s_qpos[qc] = b;      // block-uniform value, benign race
            qc++;
        } else if (c < 2 * B) {
            int cc = c - B;
            uint32_t bit = (s_tok[t * 9 + (cc >> 5)] >> (cc & 31)) & 1u;
            ak |= bit << b;
            xk |= bit << kc;
            s_kpos[kc] = b;
            kc++;
        } else {
            ap |= ((uint32_t)(t >> (c - 2 * B)) & 1u) << b;
            haspos = true;
        }
    }
    const int mk = kc;
    s_Ak[t] = ak;
    s_Ap[t] = ap;
    __syncthreads();

    const bool pathA = (!haspos) && (mk <= 8);   // block-uniform
    uint32_t parity;

    if (pathA) {
        // Expand tables: compact index -> address bits.
        {
            uint32_t e = 0;
            #pragma unroll
            for (int cb = 5; cb < 12; cb++)
                if ((t >> (cb - 5)) & 1)
                    e |= 1u << ((cb < mk) ? s_kpos[cb] : s_qpos[cb - mk]);
            s_exp_hi[t] = e;
            if (t < 32) {
                uint32_t e2 = 0;
                #pragma unroll
                for (int cb = 0; cb < 5; cb++)
                    if ((t >> cb) & 1)
                        e2 |= 1u << ((cb < mk) ? s_kpos[cb] : s_qpos[cb - mk]);
                s_exp_lo[t] = e2;
            }
        }
        __syncthreads();

        // Build permuted LUT R: R bit x = L bit expand(x).
        {
            const uint32_t alo = s_exp_lo[lane];
            #pragma unroll 4
            for (int wi = 0; wi < 32; wi++) {
                int w = warp * 32 + wi;
                uint32_t a = alo | s_exp_hi[w];
                uint32_t word = s_lut[a >> 5];
                uint32_t bal = __ballot_sync(0xffffffffu, (word >> (a & 31)) & 1u);
                if (lane == 0) s_R[w] = bal;
            }
        }

        const uint32_t pos = xq << mk;
        const uint32_t base = pos >> 5;

        if (mk <= 5) {
            uint32_t b0 = 1u << xk;
            #pragma unroll
            for (int d = 1; d < 32; d <<= 1) {
                uint32_t t0 = __shfl_up_sync(0xffffffffu, b0, d);
                if (lane >= d) b0 ^= t0;
            }
            if (lane == 31) s_wsum[warp] = b0;
            __syncthreads();   // also orders s_R stores before product reads
            #pragma unroll
            for (int pw = 0; pw < 3; pw++)
                if (pw < warp) b0 ^= s_wsum[pw];
            parity = (uint32_t)__popc((s_R[base] >> (pos & 31)) & b0) & 1u;
        } else if (mk == 6) {
            uint32_t b0 = ((xk >> 5) == 0) ? (1u << (xk & 31)) : 0u;
            uint32_t b1 = ((xk >> 5) == 1) ? (1u << (xk & 31)) : 0u;
            #pragma unroll
            for (int d = 1; d < 32; d <<= 1) {
                uint32_t t0 = __shfl_up_sync(0xffffffffu, b0, d);
                uint32_t t1 = __shfl_up_sync(0xffffffffu, b1, d);
                if (lane >= d) { b0 ^= t0; b1 ^= t1; }
            }
            if (lane == 31) { s_wsum[warp * 2] = b0; s_wsum[warp * 2 + 1] = b1; }
            __syncthreads();
            #pragma unroll
            for (int pw = 0; pw < 3; pw++)
                if (pw < warp) { b0 ^= s_wsum[pw * 2]; b1 ^= s_wsum[pw * 2 + 1]; }
            parity = (uint32_t)(__popc(s_R[base] & b0) + __popc(s_R[base + 1] & b1)) & 1u;
        } else if (mk == 7) {
            uint32_t b0 = ((xk >> 5) == 0) ? (1u << (xk & 31)) : 0u;
            uint32_t b1 = ((xk >> 5) == 1) ? (1u << (xk & 31)) : 0u;
            uint32_t b2 = ((xk >> 5) == 2) ? (1u << (xk & 31)) : 0u;
            uint32_t b3 = ((xk >> 5) == 3) ? (1u << (xk & 31)) : 0u;
            #pragma unroll
            for (int d = 1; d < 32; d <<= 1) {
                uint32_t t0 = __shfl_up_sync(0xffffffffu, b0, d);
                uint32_t t1 = __shfl_up_sync(0xffffffffu, b1, d);
                uint32_t t2 = __shfl_up_sync(0xffffffffu, b2, d);
                uint32_t t3 = __shfl_up_sync(0xffffffffu, b3, d);
                if (lane >= d) { b0 ^= t0; b1 ^= t1; b2 ^= t2; b3 ^= t3; }
            }
            if (lane == 31) {
                s_wsum[warp * 4 + 0] = b0; s_wsum[warp * 4 + 1] = b1;
                s_wsum[warp * 4 + 2] = b2; s_wsum[warp * 4 + 3] = b3;
            }
            __syncthreads();
            #pragma unroll
            for (int pw = 0; pw < 3; pw++)
                if (pw < warp) {
                    b0 ^= s_wsum[pw * 4 + 0]; b1 ^= s_wsum[pw * 4 + 1];
                    b2 ^= s_wsum[pw * 4 + 2]; b3 ^= s_wsum[pw * 4 + 3];
                }
            parity = (uint32_t)(__popc(s_R[base] & b0) + __popc(s_R[base + 1] & b1)
                              + __popc(s_R[base + 2] & b2) + __popc(s_R[base + 3] & b3)) & 1u;
        } else {  // mk == 8: 256-bit (8-word) prefix-XOR scan
            uint32_t bv[8];
            const uint32_t kw = xk >> 5;       // word index 0..7
            #pragma unroll
            for (int w = 0; w < 8; w++)
                bv[w] = (kw == (uint32_t)w) ? (1u << (xk & 31)) : 0u;
            #pragma unroll
            for (int d = 1; d < 32; d <<= 1) {
                uint32_t tv[8];
                #pragma unroll
                for (int w = 0; w < 8; w++)
                    tv[w] = __shfl_up_sync(0xffffffffu, bv[w], d);
                if (lane >= d) {
                    #pragma unroll
                    for (int w = 0; w < 8; w++) bv[w] ^= tv[w];
                }
            }
            if (lane == 31) {
                #pragma unroll
                for (int w = 0; w < 8; w++) s_wsum[warp * 8 + w] = bv[w];
            }
            __syncthreads();   // also orders s_R stores before product reads
            #pragma unroll
            for (int pw = 0; pw < 3; pw++)
                if (pw < warp) {
                    #pragma unroll
                    for (int w = 0; w < 8; w++) bv[w] ^= s_wsum[pw * 8 + w];
                }
            int cnt = 0;
            #pragma unroll
            for (int w = 0; w < 8; w++)
                cnt += __popc(s_R[base + w] & bv[w]);
            parity = (uint32_t)cnt & 1u;
        }
    } else {
        // Fallback: per-key loop.
        uint32_t p = 0;
        const int i = t;
        int j = 0;
        const int full = (i + 1) & ~3;
        #pragma unroll 2
        for (; j < full; j += 4) {
            uint4 k4 = *reinterpret_cast<const uint4*>(&s_Ak[j]);
            uint32_t a0 = aq | k4.x | s_Ap[i - j];
            uint32_t a1 = aq | k4.y | s_Ap[i - j - 1];
            uint32_t a2 = aq | k4.z | s_Ap[i - j - 2];
            uint32_t a3 = aq | k4.w | s_Ap[i - j - 3];
            uint32_t w0 = s_lut[a0 >> 5], w1 = s_lut[a1 >> 5];
            uint32_t w2 = s_lut[a2 >> 5], w3 = s_lut[a3 >> 5];
            p ^= __funnelshift_r(w0, w0, a0) ^ __funnelshift_r(w1, w1, a1)
               ^ __funnelshift_r(w2, w2, a2) ^ __funnelshift_r(w3, w3, a3);
        }
        for (; j <= i; ++j) {
            uint32_t a = aq | s_Ak[j] | s_Ap[i - j];
            uint32_t w = s_lut[a >> 5];
            p ^= __funnelshift_r(w, w, a);
        }
        parity = p & 1u;
    }

    g_headres[(size_t)(h * B + n) * S + t] = (uint8_t)parity;

    // Fused reduce — threadfence-reduction with the mandatory barrier:
    // store -> fence -> __syncthreads -> atomic. (R8/R9 bug: barrier missing.)
    __threadfence();
    __syncthreads();
    if (t == 0) {
        unsigned old = atomicAdd(&g_count[n], 1u);
        s_last = (old == H - 1) ? 1 : 0;
    }
    __syncthreads();
    if (s_last) {
        __threadfence();
        int ssum = 0;
        #pragma unroll
        for (int hh = 0; hh < H; hh++)
            ssum += (int)__ldcg((const unsigned char*)&g_headres[(size_t)(hh * B + n) * S + t]);
        out[t * B + n] = (ssum > THRESH) ? 1.0f : 0.0f;
        if (t == 0) g_count[n] = 0;   // reset for next graph replay
    }
}

extern "C" void kernel_launch(void* const* d_in, const int* in_sizes, int n_in,
                              void* d_out, int out_size)
{
    const uint32_t* tokens      = 0;
    const float*    memory      = 0;
    const uint32_t* connections = 0;

    for (int k = 0; k < n_in; k++) {
        if      (in_sizes[k] == N_TOKENS && !tokens)      tokens      = (const uint32_t*)d_in[k];
        else if (in_sizes[k] == N_MEMORY && !memory)      memory      = (const float*)d_in[k];
        else if (in_sizes[k] == N_CONN   && !connections) connections = (const uint32_t*)d_in[k];
    }
    for (int k = 0; k < n_in; k++) {
        if      (in_sizes[k] == N_TOKENS * 4 && !tokens)      tokens      = (const uint32_t*)d_in[k];
        else if (in_sizes[k] == N_MEMORY * 4 && !memory)      memory      = (const float*)d_in[k];
        else if (in_sizes[k] == N_CONN * 4   && !connections) connections = (const uint32_t*)d_in[k];
    }
    if (!tokens || !memory || !connections) {
        tokens      = (const uint32_t*)d_in[0];
        memory      = (const float*)d_in[1];
        connections = (const uint32_t*)d_in[2];
    }

    pack_tokens<<<32, 128>>>(tokens);
    soft_ram_main<<<H * B, 128>>>(memory, connections, (float*)d_out);
}

// round 13
// speedup vs baseline: 1.1754x; 1.0513x over previous
#include <cuda_runtime.h>
#include <stdint.h>

#define S   128
#define B   256
#define H   16
#define NB  12
#define LUT_WORDS 128
#define THRESH 8

#define N_TOKENS  (S * B)              // 32768
#define N_MEMORY  (H * B * (1 << NB))  // 16777216
#define N_CONN    (H * B * NB)         // 49152

__device__ uint8_t  g_headres[H * B * S];
__device__ unsigned g_count[B];
__device__ uint32_t g_tokpack[S * 8];

__device__ __forceinline__ int decode_conn(uint32_t raw) {
    return (raw <= 518u) ? (int)raw : (int)__uint_as_float(raw);
}

__global__ __launch_bounds__(128) void pack_tokens(const uint32_t* __restrict__ tokens)
{
    const int gw   = blockIdx.x * 4 + (threadIdx.x >> 5);
    const int lane = threadIdx.x & 31;
    #pragma unroll
    for (int w = 0; w < 8; w++) {
        uint32_t v   = tokens[gw * B + w * 32 + lane];
        uint32_t bal = __ballot_sync(0xffffffffu, v != 0u);
        if (lane == 0) g_tokpack[gw * 8 + w] = bal;
    }
}

// One block per (h, n). 128 threads; thread t owns query row i = t.
__global__ __launch_bounds__(128) void soft_ram_main(
    const float*    __restrict__ memory,
    const uint32_t* __restrict__ connections,
    float*          __restrict__ out)
{
    __shared__ __align__(16) uint32_t s_lut[LUT_WORDS];
    __shared__ __align__(16) uint32_t s_Ak[S];
    __shared__ uint32_t s_Ap[S];
    __shared__ uint32_t s_tok[S * 9];
    __shared__ __align__(16) uint32_t s_R[LUT_WORDS];  // permuted LUT (x_q:x_k)
    __shared__ int s_kpos[NB], s_qpos[NB];
    __shared__ __align__(16) uint32_t s_wsum[4 * 8];
    __shared__ int s_last;

    const int blk = blockIdx.x;
    const int h = blk >> 8;
    const int n = blk & 255;
    const int t = threadIdx.x;
    const int warp = t >> 5, lane = t & 31;

    // Stage packed token row (coalesced; each thread only touches row t).
    {
        const uint4* src = (const uint4*)g_tokpack;
        uint4 a = src[t * 2], b = src[t * 2 + 1];
        s_tok[t * 9 + 0] = a.x; s_tok[t * 9 + 1] = a.y;
        s_tok[t * 9 + 2] = a.z; s_tok[t * 9 + 3] = a.w;
        s_tok[t * 9 + 4] = b.x; s_tok[t * 9 + 5] = b.y;
        s_tok[t * 9 + 6] = b.z; s_tok[t * 9 + 7] = b.w;
    }

    // Binarize LUT: float4 loads + sign compare + shfl_xor OR-butterfly within
    // 8-lane segments (distances 1,2,4 never cross a segment boundary).
    {
        const float4* mem4 = (const float4*)(memory + ((size_t)(h * B + n) << NB));
        #pragma unroll
        for (int it = 0; it < 8; it++) {
            float4 v = mem4[warp * 256 + it * 32 + lane];
            uint32_t nib = (uint32_t)(v.x > 0.0f)
                         | ((uint32_t)(v.y > 0.0f) << 1)
                         | ((uint32_t)(v.z > 0.0f) << 2)
                         | ((uint32_t)(v.w > 0.0f) << 3);
            uint32_t w = nib << ((lane & 7) * 4);
            w |= __shfl_xor_sync(0xffffffffu, w, 1);
            w |= __shfl_xor_sync(0xffffffffu, w, 2);
            w |= __shfl_xor_sync(0xffffffffu, w, 4);
            if ((lane & 7) == 0) s_lut[warp * 32 + it * 4 + (lane >> 3)] = w;
        }
    }

    // Decode connections (fetched as 3x LDG.128): addr = Aq[i]|Ak[j]|Ap[i-j].
    uint32_t cw[NB];
    {
        const uint4* c4 = (const uint4*)(connections + (size_t)(h * B + n) * NB);
        uint4 ca = c4[0], cb = c4[1], cc = c4[2];
        cw[0] = ca.x; cw[1]  = ca.y; cw[2]  = ca.z; cw[3]  = ca.w;
        cw[4] = cb.x; cw[5]  = cb.y; cw[6]  = cb.z; cw[7]  = cb.w;
        cw[8] = cc.x; cw[9]  = cc.y; cw[10] = cc.z; cw[11] = cc.w;
    }
    uint32_t aq = 0, ak = 0, ap = 0, xk = 0, xq = 0;
    int kc = 0, qc = 0;
    bool haspos = false;
    #pragma unroll
    for (int b = 0; b < NB; b++) {
        int c = decode_conn(cw[b]);
        if (c < B) {
            uint32_t bit = (s_tok[t * 9 + (c >> 5)] >> (c & 31)) & 1u;
            aq |= bit << b;
            xq |= bit << qc;
            s_qpos[qc] = b;      // block-uniform value, benign race
            qc++;
        } else if (c < 2 * B) {
            int cc2 = c - B;
            uint32_t bit = (s_tok[t * 9 + (cc2 >> 5)] >> (cc2 & 31)) & 1u;
            ak |= bit << b;
            xk |= bit << kc;
            s_kpos[kc] = b;
            kc++;
        } else {
            ap |= ((uint32_t)(t >> (c - 2 * B)) & 1u) << b;
            haspos = true;
        }
    }
    const int mk = kc;
    s_Ak[t] = ak;
    s_Ap[t] = ap;
    __syncthreads();   // s_lut, s_kpos/s_qpos, s_Ak/s_Ap all ready

    const bool pathA = (!haspos) && (mk <= 8);   // block-uniform
    uint32_t parity;

    if (pathA) {
        // Register-resident expand parts (no shared tables, no extra barrier):
        // ehi = expand of bits 5..11 of t  (R-build fetches peers' via shfl)
        // alo = expand of bits 0..4 of lane
        uint32_t ehi = 0, alo = 0;
        #pragma unroll
        for (int cb2 = 5; cb2 < 12; cb2++)
            if ((t >> (cb2 - 5)) & 1)
                ehi |= 1u << ((cb2 < mk) ? s_kpos[cb2] : s_qpos[cb2 - mk]);
        #pragma unroll
        for (int cb2 = 0; cb2 < 5; cb2++)
            if ((lane >> cb2) & 1)
                alo |= 1u << ((cb2 < mk) ? s_kpos[cb2] : s_qpos[cb2 - mk]);

        // Build permuted LUT R: R bit x = L bit expand(x).
        #pragma unroll 8
        for (int wi = 0; wi < 32; wi++) {
            uint32_t a = alo | __shfl_sync(0xffffffffu, ehi, wi);
            uint32_t word = s_lut[a >> 5];
            uint32_t bal = __ballot_sync(0xffffffffu, (word >> (a & 31)) & 1u);
            if (lane == 0) s_R[warp * 32 + wi] = bal;
        }

        const uint32_t pos = xq << mk;
        const uint32_t base = pos >> 5;

        if (mk <= 5) {
            uint32_t b0 = 1u << xk;
            #pragma unroll
            for (int d = 1; d < 32; d <<= 1) {
                uint32_t t0 = __shfl_up_sync(0xffffffffu, b0, d);
                if (lane >= d) b0 ^= t0;
            }
            if (lane == 31) s_wsum[warp] = b0;
            __syncthreads();   // also orders s_R stores before product reads
            #pragma unroll
            for (int pw = 0; pw < 3; pw++)
                if (pw < warp) b0 ^= s_wsum[pw];
            parity = (uint32_t)__popc((s_R[base] >> (pos & 31)) & b0) & 1u;
        } else if (mk == 6) {
            uint32_t b0 = ((xk >> 5) == 0) ? (1u << (xk & 31)) : 0u;
            uint32_t b1 = ((xk >> 5) == 1) ? (1u << (xk & 31)) : 0u;
            #pragma unroll
            for (int d = 1; d < 32; d <<= 1) {
                uint32_t t0 = __shfl_up_sync(0xffffffffu, b0, d);
                uint32_t t1 = __shfl_up_sync(0xffffffffu, b1, d);
                if (lane >= d) { b0 ^= t0; b1 ^= t1; }
            }
            if (lane == 31) { s_wsum[warp * 2] = b0; s_wsum[warp * 2 + 1] = b1; }
            __syncthreads();
            #pragma unroll
            for (int pw = 0; pw < 3; pw++)
                if (pw < warp) { b0 ^= s_wsum[pw * 2]; b1 ^= s_wsum[pw * 2 + 1]; }
            parity = (uint32_t)(__popc(s_R[base] & b0) + __popc(s_R[base + 1] & b1)) & 1u;
        } else if (mk == 7) {
            uint32_t b0 = ((xk >> 5) == 0) ? (1u << (xk & 31)) : 0u;
            uint32_t b1 = ((xk >> 5) == 1) ? (1u << (xk & 31)) : 0u;
            uint32_t b2 = ((xk >> 5) == 2) ? (1u << (xk & 31)) : 0u;
            uint32_t b3 = ((xk >> 5) == 3) ? (1u << (xk & 31)) : 0u;
            #pragma unroll
            for (int d = 1; d < 32; d <<= 1) {
                uint32_t t0 = __shfl_up_sync(0xffffffffu, b0, d);
                uint32_t t1 = __shfl_up_sync(0xffffffffu, b1, d);
                uint32_t t2 = __shfl_up_sync(0xffffffffu, b2, d);
                uint32_t t3 = __shfl_up_sync(0xffffffffu, b3, d);
                if (lane >= d) { b0 ^= t0; b1 ^= t1; b2 ^= t2; b3 ^= t3; }
            }
            if (lane == 31) {
                s_wsum[warp * 4 + 0] = b0; s_wsum[warp * 4 + 1] = b1;
                s_wsum[warp * 4 + 2] = b2; s_wsum[warp * 4 + 3] = b3;
            }
            __syncthreads();
            #pragma unroll
            for (int pw = 0; pw < 3; pw++)
                if (pw < warp) {
                    b0 ^= s_wsum[pw * 4 + 0]; b1 ^= s_wsum[pw * 4 + 1];
                    b2 ^= s_wsum[pw * 4 + 2]; b3 ^= s_wsum[pw * 4 + 3];
                }
            uint4 r = *reinterpret_cast<const uint4*>(&s_R[base]);  // base = xq*4
            parity = (uint32_t)(__popc(r.x & b0) + __popc(r.y & b1)
                              + __popc(r.z & b2) + __popc(r.w & b3)) & 1u;
        } else {  // mk == 8: 256-bit (8-word) prefix-XOR scan
            uint32_t bv[8];
            const uint32_t kw = xk >> 5;
            #pragma unroll
            for (int w = 0; w < 8; w++)
                bv[w] = (kw == (uint32_t)w) ? (1u << (xk & 31)) : 0u;
            #pragma unroll
            for (int d = 1; d < 32; d <<= 1) {
                uint32_t tv[8];
                #pragma unroll
                for (int w = 0; w < 8; w++)
                    tv[w] = __shfl_up_sync(0xffffffffu, bv[w], d);
                if (lane >= d) {
                    #pragma unroll
                    for (int w = 0; w < 8; w++) bv[w] ^= tv[w];
                }
            }
            if (lane == 31) {
                #pragma unroll
                for (int w = 0; w < 8; w++) s_wsum[warp * 8 + w] = bv[w];
            }
            __syncthreads();
            #pragma unroll
            for (int pw = 0; pw < 3; pw++)
                if (pw < warp) {
                    #pragma unroll
                    for (int w = 0; w < 8; w++) bv[w] ^= s_wsum[pw * 8 + w];
                }
            uint4 r0 = *reinterpret_cast<const uint4*>(&s_R[base]);      // base = xq*8
            uint4 r1 = *reinterpret_cast<const uint4*>(&s_R[base + 4]);
            int cnt = __popc(r0.x & bv[0]) + __popc(r0.y & bv[1])
                    + __popc(r0.z & bv[2]) + __popc(r0.w & bv[3])
                    + __popc(r1.x & bv[4]) + __popc(r1.y & bv[5])
                    + __popc(r1.z & bv[6]) + __popc(r1.w & bv[7]);
            parity = (uint32_t)cnt & 1u;
        }
    } else {
        // Fallback: per-key loop.
        uint32_t p = 0;
        const int i = t;
        int j = 0;
        const int full = (i + 1) & ~3;
        #pragma unroll 2
        for (; j < full; j += 4) {
            uint4 k4 = *reinterpret_cast<const uint4*>(&s_Ak[j]);
            uint32_t a0 = aq | k4.x | s_Ap[i - j];
            uint32_t a1 = aq | k4.y | s_Ap[i - j - 1];
            uint32_t a2 = aq | k4.z | s_Ap[i - j - 2];
            uint32_t a3 = aq | k4.w | s_Ap[i - j - 3];
            uint32_t w0 = s_lut[a0 >> 5], w1 = s_lut[a1 >> 5];
            uint32_t w2 = s_lut[a2 >> 5], w3 = s_lut[a3 >> 5];
            p ^= __funnelshift_r(w0, w0, a0) ^ __funnelshift_r(w1, w1, a1)
               ^ __funnelshift_r(w2, w2, a2) ^ __funnelshift_r(w3, w3, a3);
        }
        for (; j <= i; ++j) {
            uint32_t a = aq | s_Ak[j] | s_Ap[i - j];
            uint32_t w = s_lut[a >> 5];
            p ^= __funnelshift_r(w, w, a);
        }
        parity = p & 1u;
    }

    g_headres[(size_t)(h * B + n) * S + t] = (uint8_t)parity;

    // Fused reduce — threadfence-reduction with the mandatory barrier:
    // store -> fence -> __syncthreads -> atomic.
    __threadfence();
    __syncthreads();
    if (t == 0) {
        unsigned old = atomicAdd(&g_count[n], 1u);
        s_last = (old == H - 1) ? 1 : 0;
    }
    __syncthreads();
    if (s_last) {
        __threadfence();
        int ssum = 0;
        #pragma unroll
        for (int hh = 0; hh < H; hh++)
            ssum += (int)__ldcg((const unsigned char*)&g_headres[(size_t)(hh * B + n) * S + t]);
        out[t * B + n] = (ssum > THRESH) ? 1.0f : 0.0f;
        if (t == 0) g_count[n] = 0;   // reset for next graph replay
    }
}

extern "C" void kernel_launch(void* const* d_in, const int* in_sizes, int n_in,
                              void* d_out, int out_size)
{
    const uint32_t* tokens      = 0;
    const float*    memory      = 0;
    const uint32_t* connections = 0;

    for (int k = 0; k < n_in; k++) {
        if      (in_sizes[k] == N_TOKENS && !tokens)      tokens      = (const uint32_t*)d_in[k];
        else if (in_sizes[k] == N_MEMORY && !memory)      memory      = (const float*)d_in[k];
        else if (in_sizes[k] == N_CONN   && !connections) connections = (const uint32_t*)d_in[k];
    }
    for (int k = 0; k < n_in; k++) {
        if      (in_sizes[k] == N_TOKENS * 4 && !tokens)      tokens      = (const uint32_t*)d_in[k];
        else if (in_sizes[k] == N_MEMORY * 4 && !memory)      memory      = (const float*)d_in[k];
        else if (in_sizes[k] == N_CONN * 4   && !connections) connections = (const uint32_t*)d_in[k];
    }
    if (!tokens || !memory || !connections) {
        tokens      = (const uint32_t*)d_in[0];
        memory      = (const float*)d_in[1];
        connections = (const uint32_t*)d_in[2];
    }

    pack_tokens<<<32, 128>>>(tokens);
    soft_ram_main<<<H * B, 128>>>(memory, connections, (float*)d_out);
}

// round 14
// speedup vs baseline: 1.1913x; 1.0135x over previous
#include <cuda_runtime.h>
#include <stdint.h>

#define S   128
#define B   256
#define H   16
#define NB  12
#define LUT_WORDS 128
#define THRESH 8

#define N_TOKENS  (S * B)              // 32768
#define N_MEMORY  (H * B * (1 << NB))  // 16777216
#define N_CONN    (H * B * NB)         // 49152

__device__ uint8_t  g_headres[H * B * S];
__device__ unsigned g_count[B];
__device__ uint32_t g_tokpack[S * 8];

__device__ __forceinline__ int decode_conn(uint32_t raw) {
    return (raw <= 518u) ? (int)raw : (int)__uint_as_float(raw);
}

__global__ __launch_bounds__(128) void pack_tokens(const uint32_t* __restrict__ tokens)
{
    const int gw   = blockIdx.x * 4 + (threadIdx.x >> 5);
    const int lane = threadIdx.x & 31;
    #pragma unroll
    for (int w = 0; w < 8; w++) {
        uint32_t v   = tokens[gw * B + w * 32 + lane];
        uint32_t bal = __ballot_sync(0xffffffffu, v != 0u);
        if (lane == 0) g_tokpack[gw * 8 + w] = bal;
    }
}

// One block per (h, n). 128 threads; thread t owns query row i = t.
__global__ __launch_bounds__(128) void soft_ram_main(
    const float*    __restrict__ memory,
    const uint32_t* __restrict__ connections,
    float*          __restrict__ out)
{
    __shared__ __align__(16) uint32_t s_lut[LUT_WORDS];
    __shared__ __align__(16) uint32_t s_Ak[S];
    __shared__ uint32_t s_Ap[S];
    __shared__ uint32_t s_Aq[S];
    __shared__ uint32_t s_part[S];             // fallback partial parities
    __shared__ uint32_t s_tok[S * 9];
    __shared__ __align__(16) uint32_t s_R[LUT_WORDS];  // permuted LUT (x_q:x_k)
    __shared__ int s_kpos[NB], s_qpos[NB];
    __shared__ __align__(16) uint32_t s_wsum[4 * 8];
    __shared__ int s_last;

    const int blk = blockIdx.x;
    const int h = blk >> 8;
    const int n = blk & 255;
    const int t = threadIdx.x;
    const int warp = t >> 5, lane = t & 31;

    // Stage packed token row (coalesced; each thread only touches row t).
    {
        const uint4* src = (const uint4*)g_tokpack;
        uint4 a = src[t * 2], b = src[t * 2 + 1];
        s_tok[t * 9 + 0] = a.x; s_tok[t * 9 + 1] = a.y;
        s_tok[t * 9 + 2] = a.z; s_tok[t * 9 + 3] = a.w;
        s_tok[t * 9 + 4] = b.x; s_tok[t * 9 + 5] = b.y;
        s_tok[t * 9 + 6] = b.z; s_tok[t * 9 + 7] = b.w;
    }

    // Binarize LUT: float4 loads + sign compare + shfl_xor OR-butterfly within
    // 8-lane segments (distances 1,2,4 never cross a segment boundary).
    {
        const float4* mem4 = (const float4*)(memory + ((size_t)(h * B + n) << NB));
        #pragma unroll
        for (int it = 0; it < 8; it++) {
            float4 v = mem4[warp * 256 + it * 32 + lane];
            uint32_t nib = (uint32_t)(v.x > 0.0f)
                         | ((uint32_t)(v.y > 0.0f) << 1)
                         | ((uint32_t)(v.z > 0.0f) << 2)
                         | ((uint32_t)(v.w > 0.0f) << 3);
            uint32_t w = nib << ((lane & 7) * 4);
            w |= __shfl_xor_sync(0xffffffffu, w, 1);
            w |= __shfl_xor_sync(0xffffffffu, w, 2);
            w |= __shfl_xor_sync(0xffffffffu, w, 4);
            if ((lane & 7) == 0) s_lut[warp * 32 + it * 4 + (lane >> 3)] = w;
        }
    }

    // Decode connections (3x LDG.128): addr = Aq[i]|Ak[j]|Ap[i-j].
    uint32_t cw[NB];
    {
        const uint4* c4 = (const uint4*)(connections + (size_t)(h * B + n) * NB);
        uint4 ca = c4[0], cb = c4[1], cc = c4[2];
        cw[0] = ca.x; cw[1]  = ca.y; cw[2]  = ca.z; cw[3]  = ca.w;
        cw[4] = cb.x; cw[5]  = cb.y; cw[6]  = cb.z; cw[7]  = cb.w;
        cw[8] = cc.x; cw[9]  = cc.y; cw[10] = cc.z; cw[11] = cc.w;
    }
    uint32_t aq = 0, ak = 0, ap = 0, xk = 0, xq = 0;
    int kc = 0, qc = 0;
    bool haspos = false;
    #pragma unroll
    for (int b = 0; b < NB; b++) {
        int c = decode_conn(cw[b]);
        if (c < B) {
            uint32_t bit = (s_tok[t * 9 + (c >> 5)] >> (c & 31)) & 1u;
            aq |= bit << b;
            xq |= bit << qc;
            s_qpos[qc] = b;      // block-uniform value, benign race
            qc++;
        } else if (c < 2 * B) {
            int cc2 = c - B;
            uint32_t bit = (s_tok[t * 9 + (cc2 >> 5)] >> (cc2 & 31)) & 1u;
            ak |= bit << b;
            xk |= bit << kc;
            s_kpos[kc] = b;
            kc++;
        } else {
            ap |= ((uint32_t)(t >> (c - 2 * B)) & 1u) << b;
            haspos = true;
        }
    }
    const int mk = kc;
    s_Ak[t] = ak;
    s_Ap[t] = ap;
    s_Aq[t] = aq;
    __syncthreads();   // s_lut, pos lists, s_Ak/s_Ap/s_Aq ready

    const bool pathA = (!haspos) && (mk <= 8);   // block-uniform

    if (pathA) {
        uint32_t parity;
        // Register-resident expand parts:
        uint32_t ehi = 0, alo = 0;
        #pragma unroll
        for (int cb2 = 5; cb2 < 12; cb2++)
            if ((t >> (cb2 - 5)) & 1)
                ehi |= 1u << ((cb2 < mk) ? s_kpos[cb2] : s_qpos[cb2 - mk]);
        #pragma unroll
        for (int cb2 = 0; cb2 < 5; cb2++)
            if ((lane >> cb2) & 1)
                alo |= 1u << ((cb2 < mk) ? s_kpos[cb2] : s_qpos[cb2 - mk]);

        // Build permuted LUT R: R bit x = L bit expand(x).
        #pragma unroll 8
        for (int wi = 0; wi < 32; wi++) {
            uint32_t a = alo | __shfl_sync(0xffffffffu, ehi, wi);
            uint32_t word = s_lut[a >> 5];
            uint32_t bal = __ballot_sync(0xffffffffu, (word >> (a & 31)) & 1u);
            if (lane == 0) s_R[warp * 32 + wi] = bal;
        }

        const uint32_t pos = xq << mk;
        const uint32_t base = pos >> 5;

        if (mk <= 5) {
            uint32_t b0 = 1u << xk;
            #pragma unroll
            for (int d = 1; d < 32; d <<= 1) {
                uint32_t t0 = __shfl_up_sync(0xffffffffu, b0, d);
                if (lane >= d) b0 ^= t0;
            }
            if (lane == 31) s_wsum[warp] = b0;
            __syncthreads();   // also orders s_R stores before product reads
            #pragma unroll
            for (int pw = 0; pw < 3; pw++)
                if (pw < warp) b0 ^= s_wsum[pw];
            parity = (uint32_t)__popc((s_R[base] >> (pos & 31)) & b0) & 1u;
        } else if (mk == 6) {
            uint32_t b0 = ((xk >> 5) == 0) ? (1u << (xk & 31)) : 0u;
            uint32_t b1 = ((xk >> 5) == 1) ? (1u << (xk & 31)) : 0u;
            #pragma unroll
            for (int d = 1; d < 32; d <<= 1) {
                uint32_t t0 = __shfl_up_sync(0xffffffffu, b0, d);
                uint32_t t1 = __shfl_up_sync(0xffffffffu, b1, d);
                if (lane >= d) { b0 ^= t0; b1 ^= t1; }
            }
            if (lane == 31) { s_wsum[warp * 2] = b0; s_wsum[warp * 2 + 1] = b1; }
            __syncthreads();
            #pragma unroll
            for (int pw = 0; pw < 3; pw++)
                if (pw < warp) { b0 ^= s_wsum[pw * 2]; b1 ^= s_wsum[pw * 2 + 1]; }
            parity = (uint32_t)(__popc(s_R[base] & b0) + __popc(s_R[base + 1] & b1)) & 1u;
        } else if (mk == 7) {
            uint32_t b0 = ((xk >> 5) == 0) ? (1u << (xk & 31)) : 0u;
            uint32_t b1 = ((xk >> 5) == 1) ? (1u << (xk & 31)) : 0u;
            uint32_t b2 = ((xk >> 5) == 2) ? (1u << (xk & 31)) : 0u;
            uint32_t b3 = ((xk >> 5) == 3) ? (1u << (xk & 31)) : 0u;
            #pragma unroll
            for (int d = 1; d < 32; d <<= 1) {
                uint32_t t0 = __shfl_up_sync(0xffffffffu, b0, d);
                uint32_t t1 = __shfl_up_sync(0xffffffffu, b1, d);
                uint32_t t2 = __shfl_up_sync(0xffffffffu, b2, d);
                uint32_t t3 = __shfl_up_sync(0xffffffffu, b3, d);
                if (lane >= d) { b0 ^= t0; b1 ^= t1; b2 ^= t2; b3 ^= t3; }
            }
            if (lane == 31) {
                s_wsum[warp * 4 + 0] = b0; s_wsum[warp * 4 + 1] = b1;
                s_wsum[warp * 4 + 2] = b2; s_wsum[warp * 4 + 3] = b3;
            }
            __syncthreads();
            #pragma unroll
            for (int pw = 0; pw < 3; pw++)
                if (pw < warp) {
                    b0 ^= s_wsum[pw * 4 + 0]; b1 ^= s_wsum[pw * 4 + 1];
                    b2 ^= s_wsum[pw * 4 + 2]; b3 ^= s_wsum[pw * 4 + 3];
                }
            uint4 r = *reinterpret_cast<const uint4*>(&s_R[base]);
            parity = (uint32_t)(__popc(r.x & b0) + __popc(r.y & b1)
                              + __popc(r.z & b2) + __popc(r.w & b3)) & 1u;
        } else {  // mk == 8
            uint32_t bv[8];
            const uint32_t kw = xk >> 5;
            #pragma unroll
            for (int w = 0; w < 8; w++)
                bv[w] = (kw == (uint32_t)w) ? (1u << (xk & 31)) : 0u;
            #pragma unroll
            for (int d = 1; d < 32; d <<= 1) {
                uint32_t tv[8];
                #pragma unroll
                for (int w = 0; w < 8; w++)
                    tv[w] = __shfl_up_sync(0xffffffffu, bv[w], d);
                if (lane >= d) {
                    #pragma unroll
                    for (int w = 0; w < 8; w++) bv[w] ^= tv[w];
                }
            }
            if (lane == 31) {
                #pragma unroll
                for (int w = 0; w < 8; w++) s_wsum[warp * 8 + w] = bv[w];
            }
            __syncthreads();
            #pragma unroll
            for (int pw = 0; pw < 3; pw++)
                if (pw < warp) {
                    #pragma unroll
                    for (int w = 0; w < 8; w++) bv[w] ^= s_wsum[pw * 8 + w];
                }
            uint4 r0 = *reinterpret_cast<const uint4*>(&s_R[base]);
            uint4 r1 = *reinterpret_cast<const uint4*>(&s_R[base + 4]);
            int cnt = __popc(r0.x & bv[0]) + __popc(r0.y & bv[1])
                    + __popc(r0.z & bv[2]) + __popc(r0.w & bv[3])
                    + __popc(r1.x & bv[4]) + __popc(r1.y & bv[5])
                    + __popc(r1.z & bv[6]) + __popc(r1.w & bv[7]);
            parity = (uint32_t)cnt & 1u;
        }
        g_headres[(size_t)(h * B + n) * S + t] = (uint8_t)parity;
    } else {
        // Balanced fallback: pair row u with row 127-u; every warp's trip
        // budget is exactly 80 (vs 128 for warp 3 in the naive triangle).
        const size_t rowbase = (size_t)(h * B + n) * S;
        if (t < 64) {
            // Full row t (keys 0..t).
            uint32_t p1 = 0;
            #pragma unroll 4
            for (int j = 0; j <= t; ++j) {
                uint32_t a = aq | s_Ak[j] | s_Ap[t - j];
                uint32_t w = s_lut[a >> 5];
                p1 ^= __funnelshift_r(w, w, a);
            }
            g_headres[rowbase + t] = (uint8_t)(p1 & 1u);
            // Partial of row r = 127-t: keys 0 .. 47-t (empty when t > 47).
            const int r = 127 - t;
            const uint32_t aqr = s_Aq[r];
            uint32_t p2 = 0;
            #pragma unroll 4
            for (int j = 0; j <= 47 - t; ++j) {
                uint32_t a = aqr | s_Ak[j] | s_Ap[r - j];
                uint32_t w = s_lut[a >> 5];
                p2 ^= __funnelshift_r(w, w, a);
            }
            s_part[r] = p2;   // unconditional (0 when empty)
        } else {
            // Row t: keys max(0, t-79) .. t (<= 80 trips).
            const int jstart = (t - 79 > 0) ? (t - 79) : 0;
            uint32_t p1 = 0;
            #pragma unroll 4
            for (int j = jstart; j <= t; ++j) {
                uint32_t a = aq | s_Ak[j] | s_Ap[t - j];
                uint32_t w = s_lut[a >> 5];
                p1 ^= __funnelshift_r(w, w, a);
            }
            s_part[t - 64] = p1;  // stash own partial in unused low slots? no:
            // store in register; barrier below then combine. (We keep p1 live.)
            __syncthreads();      // low threads' s_part writes visible
            uint32_t p = p1 ^ s_part[t];
            g_headres[rowbase + t] = (uint8_t)(p & 1u);
        }
        if (t < 64) __syncthreads();   // matching barrier (uniform per block)
    }

    // Fused reduce — threadfence-reduction with the mandatory barrier:
    // store -> fence -> __syncthreads -> atomic.
    __threadfence();
    __syncthreads();
    if (t == 0) {
        unsigned old = atomicAdd(&g_count[n], 1u);
        s_last = (old == H - 1) ? 1 : 0;
    }
    __syncthreads();
    if (s_last) {
        __threadfence();
        int ssum = 0;
        #pragma unroll
        for (int hh = 0; hh < H; hh++)
            ssum += (int)__ldcg((const unsigned char*)&g_headres[(size_t)(hh * B + n) * S + t]);
        out[t * B + n] = (ssum > THRESH) ? 1.0f : 0.0f;
        if (t == 0) g_count[n] = 0;   // reset for next graph replay
    }
}

extern "C" void kernel_launch(void* const* d_in, const int* in_sizes, int n_in,
                              void* d_out, int out_size)
{
    const uint32_t* tokens      = 0;
    const float*    memory      = 0;
    const uint32_t* connections = 0;

    for (int k = 0; k < n_in; k++) {
        if      (in_sizes[k] == N_TOKENS && !tokens)      tokens      = (const uint32_t*)d_in[k];
        else if (in_sizes[k] == N_MEMORY && !memory)      memory      = (const float*)d_in[k];
        else if (in_sizes[k] == N_CONN   && !connections) connections = (const uint32_t*)d_in[k];
    }
    for (int k = 0; k < n_in; k++) {
        if      (in_sizes[k] == N_TOKENS * 4 && !tokens)      tokens      = (const uint32_t*)d_in[k];
        else if (in_sizes[k] == N_MEMORY * 4 && !memory)      memory      = (const float*)d_in[k];
        else if (in_sizes[k] == N_CONN * 4   && !connections) connections = (const uint32_t*)d_in[k];
    }
    if (!tokens || !memory || !connections) {
        tokens      = (const uint32_t*)d_in[0];
        memory      = (const float*)d_in[1];
        connections = (const uint32_t*)d_in[2];
    }

    pack_tokens<<<32, 128>>>(tokens);
    soft_ram_main<<<H * B, 128>>>(memory, connections, (float*)d_out);
}